// round 15
// baseline (speedup 1.0000x reference)
#include <cuda_runtime.h>
#include <cstdint>

typedef unsigned long long ull;

#define Bb 2
#define Hh 48
#define Ww 48
#define DMo 192
#define Ns 16
#define DI 384
#define Rr 12
#define Kk 4
#define Ll (Hh*Ww)          // 2304
#define NCHUNK 36
#define CLEN (Ll/NCHUNK)    // 64
#define LOG2E 1.4426950408889634f
#define LN2 0.6931471805599453f

// ---------------- static device scratch ----------------
__device__ float g_xz  [(size_t)Bb*Ll*(2*DI)];
__device__ float g_xc  [(size_t)Bb*Ll*DI];
__device__ float g_c176[(size_t)Bb*Ll*176];
__device__ float g_dts [(size_t)Bb*Kk*Ll*DI];
__device__ float g_y   [(size_t)Bb*Kk*Ll*DI];       // RASTER-indexed per direction (b,k,p,d)
__device__ float g_g   [(size_t)Bb*Ll*DI];
__device__ float g_hend [(size_t)Bb*Kk*NCHUNK*DI*Ns];
__device__ float g_aprod[(size_t)Bb*Kk*NCHUNK*DI*Ns];
__device__ float g_hinit[(size_t)Bb*Kk*NCHUNK*DI*Ns];

// ---------------- helpers ----------------
__device__ __forceinline__ float ex2f(float x){ float y; asm("ex2.approx.f32 %0, %1;" : "=f"(y) : "f"(x)); return y; }
__device__ __forceinline__ float lg2f(float x){ float y; asm("lg2.approx.f32 %0, %1;" : "=f"(y) : "f"(x)); return y; }

__device__ __forceinline__ float softplus_fast(float x){
    float e = ex2f(-fabsf(x) * LOG2E);
    return fmaxf(x, 0.f) + LN2 * lg2f(1.f + e);
}
__device__ __forceinline__ float sigmoidf(float x){
    return 1.f / (1.f + __expf(-x));
}

__device__ __forceinline__ ull pk2(float lo, float hi){
    ull r; asm("mov.b64 %0, {%1, %2};" : "=l"(r) : "r"(__float_as_uint(lo)), "r"(__float_as_uint(hi)));
    return r;
}
__device__ __forceinline__ void upk2(ull v, float& lo, float& hi){
    unsigned a, b; asm("mov.b64 {%0, %1}, %2;" : "=r"(a), "=r"(b) : "l"(v));
    lo = __uint_as_float(a); hi = __uint_as_float(b);
}
__device__ __forceinline__ ull fma2(ull a, ull b, ull c){
    ull d; asm("fma.rn.f32x2 %0, %1, %2, %3;" : "=l"(d) : "l"(a), "l"(b), "l"(c));
    return d;
}
__device__ __forceinline__ ull mul2(ull a, ull b){
    ull d; asm("mul.rn.f32x2 %0, %1, %2;" : "=l"(d) : "l"(a), "l"(b));
    return d;
}

// pair powers: p[i] = (r^(2i+1), r^(2i+2)), squaring tree (depth ~3)
__device__ __forceinline__ void powers16p(float r, ull* p){
    float r2 = r*r, r4 = r2*r2, r8 = r4*r4;
    ull R2 = pk2(r2, r2), R4 = pk2(r4, r4), R8 = pk2(r8, r8);
    p[0] = pk2(r, r2);
    p[1] = mul2(p[0], R2);
    p[2] = mul2(p[0], R4);
    p[3] = mul2(p[1], R4);
    p[4] = mul2(p[0], R8);
    p[5] = mul2(p[1], R8);
    p[6] = mul2(p[2], R8);
    p[7] = mul2(p[3], R8);
}

// raster location visited at scan step l of direction k (involution)
__device__ __forceinline__ int loc_of(int k, int l){
    int l2 = (k >= 2) ? (Ll - 1 - l) : l;
    if (k & 1){ int w = l2 / Ww; int h = l2 - w * Ww; return h * Ww + w; }
    return l2;
}

// ---------------- NT GEMM, pair-over-K FFMA2 micro, optional split-K ----------------
template<int SPLITS, bool ATOMIC, bool DEP>
__device__ __forceinline__ void gemm_nt2(const float* __restrict__ A, const float* __restrict__ B,
                                         float* __restrict__ C, int K, int Nrow){
    __shared__ float As[64][20];
    __shared__ float Bs[8][132];
    int t  = threadIdx.x;
    int tx = t & 15, ty = t >> 4;
    int m0 = blockIdx.y * 64, n0 = blockIdx.x * 64;
    int klen = K / SPLITS;
    int kbeg = klen * blockIdx.z;
    ull acc[4][4] = {};
    int r  = t >> 2;
    int kc = (t & 3) << 2;
    int brow = n0 + r; if (brow >= Nrow) brow = Nrow - 1;
    const float* Ap = A + (size_t)(m0 + r) * K + kbeg + kc;
    const float* Bp = B + (size_t)brow * K + kbeg + kc;
    float4 bv = *(const float4*)Bp;      // weights: input tensor, dependency-free
    if (DEP) cudaGridDependencySynchronize();
    float4 av = *(const float4*)Ap;
    for (int k0 = 0; k0 < klen; k0 += 16){
        *(float4*)&As[r][kc] = av;
        *(ull*)&Bs[(kc>>1)+0][2*r] = pk2(bv.x, bv.y);
        *(ull*)&Bs[(kc>>1)+1][2*r] = pk2(bv.z, bv.w);
        __syncthreads();
        if (k0 + 16 < klen){
            av = *(const float4*)(Ap + k0 + 16);
            bv = *(const float4*)(Bp + k0 + 16);
        }
        #pragma unroll
        for (int kp = 0; kp < 8; kp++){
            ull a0 = *(const ull*)&As[(ty<<2)+0][kp<<1];
            ull a1 = *(const ull*)&As[(ty<<2)+1][kp<<1];
            ull a2 = *(const ull*)&As[(ty<<2)+2][kp<<1];
            ull a3 = *(const ull*)&As[(ty<<2)+3][kp<<1];
            ull b0 = *(const ull*)&Bs[kp][2*tx];
            ull b1 = *(const ull*)&Bs[kp][2*(tx+16)];
            ull b2 = *(const ull*)&Bs[kp][2*(tx+32)];
            ull b3 = *(const ull*)&Bs[kp][2*(tx+48)];
            acc[0][0]=fma2(a0,b0,acc[0][0]); acc[0][1]=fma2(a0,b1,acc[0][1]);
            acc[0][2]=fma2(a0,b2,acc[0][2]); acc[0][3]=fma2(a0,b3,acc[0][3]);
            acc[1][0]=fma2(a1,b0,acc[1][0]); acc[1][1]=fma2(a1,b1,acc[1][1]);
            acc[1][2]=fma2(a1,b2,acc[1][2]); acc[1][3]=fma2(a1,b3,acc[1][3]);
            acc[2][0]=fma2(a2,b0,acc[2][0]); acc[2][1]=fma2(a2,b1,acc[2][1]);
            acc[2][2]=fma2(a2,b2,acc[2][2]); acc[2][3]=fma2(a2,b3,acc[2][3]);
            acc[3][0]=fma2(a3,b0,acc[3][0]); acc[3][1]=fma2(a3,b1,acc[3][1]);
            acc[3][2]=fma2(a3,b2,acc[3][2]); acc[3][3]=fma2(a3,b3,acc[3][3]);
        }
        __syncthreads();
    }
    #pragma unroll
    for (int i = 0; i < 4; i++){
        int m = m0 + (ty<<2) + i;
        #pragma unroll
        for (int j = 0; j < 4; j++){
            int n = n0 + tx + 16*j;
            if (n < Nrow){
                float lo, hi; upk2(acc[i][j], lo, hi);
                if (ATOMIC) atomicAdd(&C[(size_t)m * Nrow + n], lo + hi);
                else        C[(size_t)m * Nrow + n] = lo + hi;
            }
        }
    }
    cudaTriggerProgrammaticLaunchCompletion();
}

// k_inproj also zeroes g_c176 (split-K accumulation target of k_cproj)
__global__ void __launch_bounds__(256, 3) k_inproj(const float* __restrict__ x, const float* __restrict__ w){
    {
        size_t nt = (size_t)gridDim.x * gridDim.y * 256;
        size_t gid = ((size_t)blockIdx.y * gridDim.x + blockIdx.x) * 256 + threadIdx.x;
        const size_t n4 = (size_t)Bb*Ll*176/4;
        float4 z = make_float4(0.f,0.f,0.f,0.f);
        for (size_t i = gid; i < n4; i += nt) ((float4*)g_c176)[i] = z;
    }
    gemm_nt2<1, false, false>(x, w, g_xz, DMo, 2*DI);
}
__global__ void __launch_bounds__(256, 3) k_outproj(const float* __restrict__ w, float* __restrict__ out){
    gemm_nt2<2, true, true>(g_g, w, out, DI, DMo);
}
__global__ void __launch_bounds__(256, 3) k_cproj(const float* __restrict__ xproj){
    gemm_nt2<2, true, true>(g_xc, xproj, g_c176, DI, 176);
}

// ---------------- depthwise conv 3x3 + bias + SiLU (channel-last) ----------------
__global__ void k_conv(const float* __restrict__ cw, const float* __restrict__ cb){
    int p = blockIdx.x % Ll;
    int b = blockIdx.x / Ll;
    int h = p / Ww, w = p % Ww;
    float biasv[3]; float wreg[3][9];
    #pragma unroll
    for (int j = 0; j < 3; j++){
        int d = threadIdx.x + j * 128;
        biasv[j] = cb[d];
        #pragma unroll
        for (int q = 0; q < 9; q++) wreg[j][q] = cw[d * 9 + q];
    }
    cudaGridDependencySynchronize();
    const float* base = g_xz + (size_t)b * Ll * (2*DI);
    #pragma unroll
    for (int j = 0; j < 3; j++){
        int d = threadIdx.x + j * 128;
        float acc = biasv[j];
        #pragma unroll
        for (int dh = -1; dh <= 1; dh++){
            int hh = h + dh;
            if ((unsigned)hh >= (unsigned)Hh) continue;
            #pragma unroll
            for (int dw = -1; dw <= 1; dw++){
                int ww2 = w + dw;
                if ((unsigned)ww2 >= (unsigned)Ww) continue;
                acc = fmaf(base[(size_t)(hh*Ww + ww2) * (2*DI) + d], wreg[j][(dh+1)*3 + (dw+1)], acc);
            }
        }
        g_xc[((size_t)b*Ll + p) * DI + d] = acc * sigmoidf(acc);
    }
    cudaTriggerProgrammaticLaunchCompletion();
}

// ---------------- dt projection + bias + softplus: 32-row tiles (wave-balanced) ----------------
__global__ void k_dts(const float* __restrict__ dtw, const float* __restrict__ dtb){
    __shared__ float sct[Rr][34];
    int l0 = blockIdx.x * 32;
    int k = blockIdx.y, b = blockIdx.z;
    int t = threadIdx.x;
    int d = t;
    size_t bkL = (size_t)(b*Kk + k) * Ll;
    const float* cbase = g_c176 + (size_t)b * Ll * 176 + k * 44;

    // prologue: weights/bias (inputs)
    ull w2[Rr];
    #pragma unroll
    for (int r = 0; r < Rr; r++){
        float wv = dtw[((size_t)k*DI + d) * Rr + r];
        w2[r] = pk2(wv, wv);
    }
    float bias = dtb[k*DI + d];
    ull bias2 = pk2(bias, bias);

    cudaGridDependencySynchronize();
    if (t < 32*Rr){
        int row = t / Rr, col = t - row * Rr;
        sct[col][row] = cbase[(size_t)loc_of(k, l0 + row) * 176 + col];
    }
    __syncthreads();

    float* dp = g_dts + (bkL + l0) * DI + d;
    #pragma unroll 4
    for (int lp = 0; lp < 16; lp++){
        ull acc = bias2;
        #pragma unroll
        for (int r = 0; r < Rr; r++){
            ull cpair = *(const ull*)&sct[r][2*lp];
            acc = fma2(w2[r], cpair, acc);
        }
        float a0, a1; upk2(acc, a0, a1);
        dp[(size_t)(2*lp)   * DI] = softplus_fast(a0);
        dp[(size_t)(2*lp+1) * DI] = softplus_fast(a1);
    }
    cudaTriggerProgrammaticLaunchCompletion();
}

// ---------------- scan position iterator ----------------
struct PosIter {
    int k, p, hh, ww;
    __device__ __forceinline__ void init(int k_, int l0){
        k = k_;
        if (k == 0){ p = l0; }
        else if (k == 2){ p = Ll - 1 - l0; }
        else {
            int l2 = (k == 1) ? l0 : (Ll - 1 - l0);
            ww = l2 / Ww; hh = l2 - ww * Ww; p = hh * Ww + ww;
        }
    }
    __device__ __forceinline__ void next(){
        if (k == 0) p++;
        else if (k == 2) p--;
        else if (k == 1){
            hh++; if (hh == Hh){ hh = 0; ww++; }
            p = hh * Ww + ww;
        } else {
            hh--; if (hh < 0){ hh = Hh - 1; ww--; }
            p = hh * Ww + ww;
        }
    }
};

// geo check without keeping A2[] live
__device__ __forceinline__ bool geo_check(const float* Ar, float& A1){
    A1 = -expf(Ar[0]) * LOG2E;
    bool geo = (A1 != 0.f);
    #pragma unroll
    for (int n = 1; n < Ns; n++){
        float an = -expf(Ar[n]) * LOG2E;
        geo = geo && (fabsf(an - (float)(n+1)*A1) <= 1e-4f * fabsf(an));
    }
    return geo;
}

// ---------------- selective scan, chunked ----------------
__global__ void __launch_bounds__(DI, 2) k_scanA(const float* __restrict__ A_logs){
    int blk = blockIdx.x;
    int chunk = blk % NCHUNK;
    int bk = blk / NCHUNK;
    int k = bk & 3, b = bk >> 2;
    int d = threadIdx.x;

    const float* Ar = A_logs + (size_t)(k*DI + d) * Ns;
    float A1;
    bool geo = geo_check(Ar, A1);      // input-only prologue
    cudaGridDependencySynchronize();

    int l0 = chunk * CLEN;
    size_t bkL = (size_t)bk * Ll;
    const float* dtp = g_dts + (bkL + l0) * DI + d;
    const float* xcb = g_xc + (size_t)b * Ll * DI + d;
    const float* cbase = g_c176 + (size_t)b * Ll * 176 + k * 44;
    size_t o = ((size_t)blk * DI + d) * Ns;

    PosIter it; it.init(k, l0);

    if (geo){
        float rp = 1.f;
        ull h2[8] = {};
        for (int s = 0; s < CLEN; s++){
            int p = it.p;
            float delta = dtp[0];
            float u = __ldg(xcb + (size_t)p * DI);
            float du = delta * u;
            float r = ex2f(delta * A1);
            ull pw[8]; powers16p(r, pw);
            const float* cp = cbase + (size_t)p * 176;
            ulonglong2 bA = *(const ulonglong2*)(cp + 12);
            ulonglong2 bB = *(const ulonglong2*)(cp + 16);
            ulonglong2 bC = *(const ulonglong2*)(cp + 20);
            ulonglong2 bD = *(const ulonglong2*)(cp + 24);
            ull dup = pk2(du, du);
            h2[0] = fma2(pw[0], h2[0], mul2(dup, bA.x));
            h2[1] = fma2(pw[1], h2[1], mul2(dup, bA.y));
            h2[2] = fma2(pw[2], h2[2], mul2(dup, bB.x));
            h2[3] = fma2(pw[3], h2[3], mul2(dup, bB.y));
            h2[4] = fma2(pw[4], h2[4], mul2(dup, bC.x));
            h2[5] = fma2(pw[5], h2[5], mul2(dup, bC.y));
            h2[6] = fma2(pw[6], h2[6], mul2(dup, bD.x));
            h2[7] = fma2(pw[7], h2[7], mul2(dup, bD.y));
            rp *= r;
            dtp += DI;
            it.next();
        }
        ull ap2[8]; powers16p(rp, ap2);
        ulonglong2* he = (ulonglong2*)(g_hend + o);
        ulonglong2* av = (ulonglong2*)(g_aprod + o);
        #pragma unroll
        for (int q = 0; q < 4; q++){
            ulonglong2 v1; v1.x = h2[2*q]; v1.y = h2[2*q+1]; he[q] = v1;
            ulonglong2 v2; v2.x = ap2[2*q]; v2.y = ap2[2*q+1]; av[q] = v2;
        }
    } else {
        float A2[Ns];
        #pragma unroll
        for (int n = 0; n < Ns; n++) A2[n] = -expf(Ar[n]) * LOG2E;
        float h[Ns], ap[Ns];
        #pragma unroll
        for (int n = 0; n < Ns; n++){ h[n] = 0.f; ap[n] = 1.f; }
        for (int s = 0; s < CLEN; s++){
            int p = it.p;
            float delta = dtp[0];
            float u = __ldg(xcb + (size_t)p * DI);
            float du = delta * u;
            const float* cp = cbase + (size_t)p * 176;
            float Bv[Ns];
            *(float4*)&Bv[0]  = *(const float4*)(cp + 12);
            *(float4*)&Bv[4]  = *(const float4*)(cp + 16);
            *(float4*)&Bv[8]  = *(const float4*)(cp + 20);
            *(float4*)&Bv[12] = *(const float4*)(cp + 24);
            #pragma unroll
            for (int n = 0; n < Ns; n++){
                float dA = ex2f(delta * A2[n]);
                h[n] = fmaf(dA, h[n], du * Bv[n]);
                ap[n] *= dA;
            }
            dtp += DI;
            it.next();
        }
        float4* he = (float4*)(g_hend + o);
        float4* av = (float4*)(g_aprod + o);
        #pragma unroll
        for (int q = 0; q < 4; q++){
            he[q] = make_float4(h[4*q], h[4*q+1], h[4*q+2], h[4*q+3]);
            av[q] = make_float4(ap[4*q], ap[4*q+1], ap[4*q+2], ap[4*q+3]);
        }
    }
    cudaTriggerProgrammaticLaunchCompletion();
}

// pass B: sequential scan over chunks -> h_init per chunk
__global__ void k_scanB(){
    cudaGridDependencySynchronize();
    int gid = blockIdx.x * blockDim.x + threadIdx.x;
    int dn = gid % (DI*Ns);
    int bk = gid / (DI*Ns);
    size_t base = (size_t)bk * NCHUNK * DI * Ns + dn;
    float hr = 0.f;
    #pragma unroll 4
    for (int c = 0; c < NCHUNK; c++){
        size_t idx = base + (size_t)c * DI * Ns;
        g_hinit[idx] = hr;
        hr = g_aprod[idx] * hr + g_hend[idx];
    }
    cudaTriggerProgrammaticLaunchCompletion();
}

// pass C: replay with correct h_init, write y at RASTER position
__global__ void __launch_bounds__(DI, 2) k_scanC(const float* __restrict__ A_logs,
                                                 const float* __restrict__ Ds){
    int blk = blockIdx.x;
    int chunk = blk % NCHUNK;
    int bk = blk / NCHUNK;
    int k = bk & 3, b = bk >> 2;
    int d = threadIdx.x;

    const float* Ar = A_logs + (size_t)(k*DI + d) * Ns;
    float A1;
    bool geo = geo_check(Ar, A1);      // input-only prologue
    float Dv = Ds[k*DI + d];
    cudaGridDependencySynchronize();

    int l0 = chunk * CLEN;
    size_t bkL = (size_t)bk * Ll;
    const float* dtp = g_dts + (bkL + l0) * DI + d;
    const float* xcb = g_xc + (size_t)b * Ll * DI + d;
    const float* cbase = g_c176 + (size_t)b * Ll * 176 + k * 44;
    float* ybase = g_y + bkL * DI + d;
    size_t o = ((size_t)blk * DI + d) * Ns;

    PosIter it; it.init(k, l0);

    if (geo){
        ull h2[8];
        {
            const ulonglong2* hi = (const ulonglong2*)(g_hinit + o);
            #pragma unroll
            for (int q = 0; q < 4; q++){ ulonglong2 v = hi[q]; h2[2*q] = v.x; h2[2*q+1] = v.y; }
        }
        for (int s = 0; s < CLEN; s++){
            int p = it.p;
            float delta = dtp[0];
            float u = __ldg(xcb + (size_t)p * DI);
            float du = delta * u;
            float r = ex2f(delta * A1);
            ull pw[8]; powers16p(r, pw);
            const float* cp = cbase + (size_t)p * 176;
            ulonglong2 bA = *(const ulonglong2*)(cp + 12);
            ulonglong2 bB = *(const ulonglong2*)(cp + 16);
            ulonglong2 bC = *(const ulonglong2*)(cp + 20);
            ulonglong2 bD = *(const ulonglong2*)(cp + 24);
            ulonglong2 cA = *(const ulonglong2*)(cp + 28);
            ulonglong2 cB = *(const ulonglong2*)(cp + 32);
            ulonglong2 cC = *(const ulonglong2*)(cp + 36);
            ulonglong2 cD = *(const ulonglong2*)(cp + 40);
            ull dup = pk2(du, du);
            h2[0] = fma2(pw[0], h2[0], mul2(dup, bA.x));
            h2[1] = fma2(pw[1], h2[1], mul2(dup, bA.y));
            h2[2] = fma2(pw[2], h2[2], mul2(dup, bB.x));
            h2[3] = fma2(pw[3], h2[3], mul2(dup, bB.y));
            h2[4] = fma2(pw[4], h2[4], mul2(dup, bC.x));
            h2[5] = fma2(pw[5], h2[5], mul2(dup, bC.y));
            h2[6] = fma2(pw[6], h2[6], mul2(dup, bD.x));
            h2[7] = fma2(pw[7], h2[7], mul2(dup, bD.y));
            ull acc2 = mul2(h2[0], cA.x);
            acc2 = fma2(h2[1], cA.y, acc2);
            acc2 = fma2(h2[2], cB.x, acc2);
            acc2 = fma2(h2[3], cB.y, acc2);
            acc2 = fma2(h2[4], cC.x, acc2);
            acc2 = fma2(h2[5], cC.y, acc2);
            acc2 = fma2(h2[6], cD.x, acc2);
            acc2 = fma2(h2[7], cD.y, acc2);
            float alo, ahi; upk2(acc2, alo, ahi);
            ybase[(size_t)p * DI] = fmaf(Dv, u, alo + ahi);
            dtp += DI;
            it.next();
        }
    } else {
        float A2[Ns];
        #pragma unroll
        for (int n = 0; n < Ns; n++) A2[n] = -expf(Ar[n]) * LOG2E;
        float h[Ns];
        {
            const float4* hi = (const float4*)(g_hinit + o);
            #pragma unroll
            for (int q = 0; q < 4; q++){
                float4 v = hi[q];
                h[4*q] = v.x; h[4*q+1] = v.y; h[4*q+2] = v.z; h[4*q+3] = v.w;
            }
        }
        for (int s = 0; s < CLEN; s++){
            int p = it.p;
            float delta = dtp[0];
            float u = __ldg(xcb + (size_t)p * DI);
            float du = delta * u;
            const float* cp = cbase + (size_t)p * 176;
            float acc = 0.f;
            #pragma unroll
            for (int q = 0; q < 4; q++){
                float4 bq = *(const float4*)(cp + 12 + 4*q);
                float4 cq = *(const float4*)(cp + 28 + 4*q);
                float dA0 = ex2f(delta * A2[4*q+0]);
                float dA1 = ex2f(delta * A2[4*q+1]);
                float dA2 = ex2f(delta * A2[4*q+2]);
                float dA3 = ex2f(delta * A2[4*q+3]);
                h[4*q+0] = fmaf(dA0, h[4*q+0], du * bq.x); acc = fmaf(h[4*q+0], cq.x, acc);
                h[4*q+1] = fmaf(dA1, h[4*q+1], du * bq.y); acc = fmaf(h[4*q+1], cq.y, acc);
                h[4*q+2] = fmaf(dA2, h[4*q+2], du * bq.z); acc = fmaf(h[4*q+2], cq.z, acc);
                h[4*q+3] = fmaf(dA3, h[4*q+3], du * bq.w); acc = fmaf(h[4*q+3], cq.w, acc);
            }
            ybase[(size_t)p * DI] = fmaf(Dv, u, acc);
            dtp += DI;
            it.next();
        }
    }
    cudaTriggerProgrammaticLaunchCompletion();
}

// ---------------- merge 4 directions + LayerNorm + gate; also zeroes d_out ----------------
__global__ void k_ln(const float* __restrict__ gam, const float* __restrict__ bet,
                     float* __restrict__ out, int out_n){
    int t = threadIdx.x;
    {
        int nt = gridDim.x * 128;
        int gid = blockIdx.x * 128 + t;
        for (int i = gid; i < out_n; i += nt) out[i] = 0.f;
    }
    float gm[3], bt[3];
    #pragma unroll
    for (int j = 0; j < 3; j++){ gm[j] = gam[t + j*128]; bt[j] = bet[t + j*128]; }
    cudaGridDependencySynchronize();

    int p = blockIdx.x % Ll;
    int b = blockIdx.x / Ll;
    const float* y0 = g_y + (((size_t)(b*Kk + 0) * Ll) + p) * DI;
    const float* y1 = y0 + (size_t)Ll * DI;
    const float* y2 = y1 + (size_t)Ll * DI;
    const float* y3 = y2 + (size_t)Ll * DI;
    float v[3];
    float s1 = 0.f, s2 = 0.f;
    #pragma unroll
    for (int j = 0; j < 3; j++){
        int d = t + j * 128;
        float y = y0[d] + y1[d] + y2[d] + y3[d];
        v[j] = y; s1 += y; s2 += y*y;
    }
    #pragma unroll
    for (int off = 16; off > 0; off >>= 1){
        s1 += __shfl_xor_sync(0xffffffffu, s1, off);
        s2 += __shfl_xor_sync(0xffffffffu, s2, off);
    }
    __shared__ float r1[4], r2[4];
    int warp = t >> 5, lane = t & 31;
    if (lane == 0){ r1[warp] = s1; r2[warp] = s2; }
    __syncthreads();
    float S1 = r1[0] + r1[1] + r1[2] + r1[3];
    float S2 = r2[0] + r2[1] + r2[2] + r2[3];
    float mu = S1 * (1.f / DI);
    float var = S2 * (1.f / DI) - mu * mu;
    float rstd = rsqrtf(var + 1e-5f);
    const float* zrow = g_xz + ((size_t)b*Ll + p) * (2*DI) + DI;
    float* grow = g_g + ((size_t)b*Ll + p) * DI;
    #pragma unroll
    for (int j = 0; j < 3; j++){
        int d = t + j * 128;
        float zn = zrow[d];
        float gate = zn * sigmoidf(zn);
        grow[d] = ((v[j] - mu) * rstd * gm[j] + bt[j]) * gate;
    }
    cudaTriggerProgrammaticLaunchCompletion();
}

// ---------------- launch (PDL chain) ----------------
template<typename K, typename... Args>
static inline void launch_pdl(K kern, dim3 g, dim3 b, Args... args){
    cudaLaunchConfig_t cfg = {};
    cfg.gridDim = g; cfg.blockDim = b; cfg.dynamicSmemBytes = 0; cfg.stream = 0;
    cudaLaunchAttribute attr[1];
    attr[0].id = cudaLaunchAttributeProgrammaticStreamSerialization;
    attr[0].val.programmaticStreamSerializationAllowed = 1;
    cfg.attrs = attr; cfg.numAttrs = 1;
    cudaLaunchKernelEx(&cfg, kern, args...);
}

extern "C" void kernel_launch(void* const* d_in, const int* in_sizes, int n_in,
                              void* d_out, int out_size){
    const float* x      = (const float*)d_in[0];
    const float* in_w   = (const float*)d_in[1];
    const float* conv_w = (const float*)d_in[2];
    const float* conv_b = (const float*)d_in[3];
    const float* xproj  = (const float*)d_in[4];
    const float* dtw    = (const float*)d_in[5];
    const float* dtb    = (const float*)d_in[6];
    const float* Alog   = (const float*)d_in[7];
    const float* Ds     = (const float*)d_in[8];
    const float* gam    = (const float*)d_in[9];
    const float* bet    = (const float*)d_in[10];
    const float* outw   = (const float*)d_in[11];
    float* out = (float*)d_out;

    k_inproj <<<dim3((2*DI)/64, (Bb*Ll)/64), 256>>>(x, in_w);
    launch_pdl(k_conv,    dim3(Bb*Ll), dim3(128), conv_w, conv_b);
    launch_pdl(k_cproj,   dim3(3, (Bb*Ll)/64, 2), dim3(256), xproj);
    launch_pdl(k_dts,     dim3(Ll/32, Kk, Bb), dim3(DI), dtw, dtb);
    launch_pdl(k_scanA,   dim3(Bb*Kk*NCHUNK), dim3(DI), Alog);
    launch_pdl(k_scanB,   dim3((Bb*Kk*DI*Ns)/256), dim3(256));
    launch_pdl(k_scanC,   dim3(Bb*Kk*NCHUNK), dim3(DI), Alog, Ds);
    launch_pdl(k_ln,      dim3(Bb*Ll), dim3(128), gam, bet, out, out_size);
    launch_pdl(k_outproj, dim3(DMo/64, (Bb*Ll)/64, 2), dim3(256), outw, out);
}

// round 16
// speedup vs baseline: 1.0203x; 1.0203x over previous
#include <cuda_runtime.h>
#include <cstdint>

typedef unsigned long long ull;

#define Bb 2
#define Hh 48
#define Ww 48
#define DMo 192
#define Ns 16
#define DI 384
#define Rr 12
#define Kk 4
#define Ll (Hh*Ww)          // 2304
#define NCHUNK 36
#define CLEN (Ll/NCHUNK)    // 64
#define LOG2E 1.4426950408889634f
#define LN2 0.6931471805599453f

// ---------------- static device scratch ----------------
__device__ float g_xz  [(size_t)Bb*Ll*(2*DI)];
__device__ float g_xc  [(size_t)Bb*Ll*DI];
__device__ float g_c176[(size_t)Bb*Ll*176];
__device__ float g_dts [(size_t)Bb*Kk*Ll*DI];
__device__ float g_y   [(size_t)Bb*Kk*Ll*DI];       // RASTER-indexed per direction (b,k,p,d)
__device__ float g_g   [(size_t)Bb*Ll*DI];
__device__ float g_hend [(size_t)Bb*Kk*NCHUNK*DI*Ns];
__device__ float g_aprod[(size_t)Bb*Kk*NCHUNK*DI*Ns];
__device__ float g_hinit[(size_t)Bb*Kk*NCHUNK*DI*Ns];

// ---------------- helpers ----------------
__device__ __forceinline__ float ex2f(float x){ float y; asm("ex2.approx.f32 %0, %1;" : "=f"(y) : "f"(x)); return y; }
__device__ __forceinline__ float lg2f(float x){ float y; asm("lg2.approx.f32 %0, %1;" : "=f"(y) : "f"(x)); return y; }

__device__ __forceinline__ float softplus_fast(float x){
    float e = ex2f(-fabsf(x) * LOG2E);
    return fmaxf(x, 0.f) + LN2 * lg2f(1.f + e);
}
__device__ __forceinline__ float sigmoidf(float x){
    return 1.f / (1.f + __expf(-x));
}

__device__ __forceinline__ ull pk2(float lo, float hi){
    ull r; asm("mov.b64 %0, {%1, %2};" : "=l"(r) : "r"(__float_as_uint(lo)), "r"(__float_as_uint(hi)));
    return r;
}
__device__ __forceinline__ void upk2(ull v, float& lo, float& hi){
    unsigned a, b; asm("mov.b64 {%0, %1}, %2;" : "=r"(a), "=r"(b) : "l"(v));
    lo = __uint_as_float(a); hi = __uint_as_float(b);
}
__device__ __forceinline__ ull fma2(ull a, ull b, ull c){
    ull d; asm("fma.rn.f32x2 %0, %1, %2, %3;" : "=l"(d) : "l"(a), "l"(b), "l"(c));
    return d;
}
__device__ __forceinline__ ull mul2(ull a, ull b){
    ull d; asm("mul.rn.f32x2 %0, %1, %2;" : "=l"(d) : "l"(a), "l"(b));
    return d;
}

// pair powers: p[i] = (r^(2i+1), r^(2i+2)), squaring tree (depth ~3)
__device__ __forceinline__ void powers16p(float r, ull* p){
    float r2 = r*r, r4 = r2*r2, r8 = r4*r4;
    ull R2 = pk2(r2, r2), R4 = pk2(r4, r4), R8 = pk2(r8, r8);
    p[0] = pk2(r, r2);
    p[1] = mul2(p[0], R2);
    p[2] = mul2(p[0], R4);
    p[3] = mul2(p[1], R4);
    p[4] = mul2(p[0], R8);
    p[5] = mul2(p[1], R8);
    p[6] = mul2(p[2], R8);
    p[7] = mul2(p[3], R8);
}

// raster location visited at scan step l of direction k (involution)
__device__ __forceinline__ int loc_of(int k, int l){
    int l2 = (k >= 2) ? (Ll - 1 - l) : l;
    if (k & 1){ int w = l2 / Ww; int h = l2 - w * Ww; return h * Ww + w; }
    return l2;
}

// ---------------- NT GEMM, pair-over-K FFMA2 micro, optional split-K ----------------
template<int SPLITS, bool ATOMIC, bool DEP>
__device__ __forceinline__ void gemm_nt2(const float* __restrict__ A, const float* __restrict__ B,
                                         float* __restrict__ C, int K, int Nrow){
    __shared__ float As[64][20];
    __shared__ float Bs[8][132];
    int t  = threadIdx.x;
    int tx = t & 15, ty = t >> 4;
    int m0 = blockIdx.y * 64, n0 = blockIdx.x * 64;
    int klen = K / SPLITS;
    int kbeg = klen * blockIdx.z;
    ull acc[4][4] = {};
    int r  = t >> 2;
    int kc = (t & 3) << 2;
    int brow = n0 + r; if (brow >= Nrow) brow = Nrow - 1;
    const float* Ap = A + (size_t)(m0 + r) * K + kbeg + kc;
    const float* Bp = B + (size_t)brow * K + kbeg + kc;
    float4 bv = *(const float4*)Bp;      // weights: input tensor, dependency-free
    if (DEP) cudaGridDependencySynchronize();
    float4 av = *(const float4*)Ap;
    for (int k0 = 0; k0 < klen; k0 += 16){
        *(float4*)&As[r][kc] = av;
        *(ull*)&Bs[(kc>>1)+0][2*r] = pk2(bv.x, bv.y);
        *(ull*)&Bs[(kc>>1)+1][2*r] = pk2(bv.z, bv.w);
        __syncthreads();
        if (k0 + 16 < klen){
            av = *(const float4*)(Ap + k0 + 16);
            bv = *(const float4*)(Bp + k0 + 16);
        }
        #pragma unroll
        for (int kp = 0; kp < 8; kp++){
            ull a0 = *(const ull*)&As[(ty<<2)+0][kp<<1];
            ull a1 = *(const ull*)&As[(ty<<2)+1][kp<<1];
            ull a2 = *(const ull*)&As[(ty<<2)+2][kp<<1];
            ull a3 = *(const ull*)&As[(ty<<2)+3][kp<<1];
            ull b0 = *(const ull*)&Bs[kp][2*tx];
            ull b1 = *(const ull*)&Bs[kp][2*(tx+16)];
            ull b2 = *(const ull*)&Bs[kp][2*(tx+32)];
            ull b3 = *(const ull*)&Bs[kp][2*(tx+48)];
            acc[0][0]=fma2(a0,b0,acc[0][0]); acc[0][1]=fma2(a0,b1,acc[0][1]);
            acc[0][2]=fma2(a0,b2,acc[0][2]); acc[0][3]=fma2(a0,b3,acc[0][3]);
            acc[1][0]=fma2(a1,b0,acc[1][0]); acc[1][1]=fma2(a1,b1,acc[1][1]);
            acc[1][2]=fma2(a1,b2,acc[1][2]); acc[1][3]=fma2(a1,b3,acc[1][3]);
            acc[2][0]=fma2(a2,b0,acc[2][0]); acc[2][1]=fma2(a2,b1,acc[2][1]);
            acc[2][2]=fma2(a2,b2,acc[2][2]); acc[2][3]=fma2(a2,b3,acc[2][3]);
            acc[3][0]=fma2(a3,b0,acc[3][0]); acc[3][1]=fma2(a3,b1,acc[3][1]);
            acc[3][2]=fma2(a3,b2,acc[3][2]); acc[3][3]=fma2(a3,b3,acc[3][3]);
        }
        __syncthreads();
    }
    #pragma unroll
    for (int i = 0; i < 4; i++){
        int m = m0 + (ty<<2) + i;
        #pragma unroll
        for (int j = 0; j < 4; j++){
            int n = n0 + tx + 16*j;
            if (n < Nrow){
                float lo, hi; upk2(acc[i][j], lo, hi);
                if (ATOMIC) atomicAdd(&C[(size_t)m * Nrow + n], lo + hi);
                else        C[(size_t)m * Nrow + n] = lo + hi;
            }
        }
    }
}

// k_inproj also zeroes g_c176 (split-K accumulation target of k_cproj)
__global__ void __launch_bounds__(256, 3) k_inproj(const float* __restrict__ x, const float* __restrict__ w){
    {
        size_t nt = (size_t)gridDim.x * gridDim.y * 256;
        size_t gid = ((size_t)blockIdx.y * gridDim.x + blockIdx.x) * 256 + threadIdx.x;
        const size_t n4 = (size_t)Bb*Ll*176/4;
        float4 z = make_float4(0.f,0.f,0.f,0.f);
        for (size_t i = gid; i < n4; i += nt) ((float4*)g_c176)[i] = z;
    }
    gemm_nt2<1, false, false>(x, w, g_xz, DMo, 2*DI);
}
__global__ void __launch_bounds__(256, 3) k_outproj(const float* __restrict__ w, float* __restrict__ out){
    gemm_nt2<2, true, true>(g_g, w, out, DI, DMo);
}
__global__ void __launch_bounds__(256, 3) k_cproj(const float* __restrict__ xproj){
    gemm_nt2<2, true, true>(g_xc, xproj, g_c176, DI, 176);
}

// ---------------- depthwise conv 3x3 + bias + SiLU (channel-last) ----------------
__global__ void k_conv(const float* __restrict__ cw, const float* __restrict__ cb){
    int p = blockIdx.x % Ll;
    int b = blockIdx.x / Ll;
    int h = p / Ww, w = p % Ww;
    float biasv[3]; float wreg[3][9];
    #pragma unroll
    for (int j = 0; j < 3; j++){
        int d = threadIdx.x + j * 128;
        biasv[j] = cb[d];
        #pragma unroll
        for (int q = 0; q < 9; q++) wreg[j][q] = cw[d * 9 + q];
    }
    cudaGridDependencySynchronize();
    const float* base = g_xz + (size_t)b * Ll * (2*DI);
    #pragma unroll
    for (int j = 0; j < 3; j++){
        int d = threadIdx.x + j * 128;
        float acc = biasv[j];
        #pragma unroll
        for (int dh = -1; dh <= 1; dh++){
            int hh = h + dh;
            if ((unsigned)hh >= (unsigned)Hh) continue;
            #pragma unroll
            for (int dw = -1; dw <= 1; dw++){
                int ww2 = w + dw;
                if ((unsigned)ww2 >= (unsigned)Ww) continue;
                acc = fmaf(base[(size_t)(hh*Ww + ww2) * (2*DI) + d], wreg[j][(dh+1)*3 + (dw+1)], acc);
            }
        }
        g_xc[((size_t)b*Ll + p) * DI + d] = acc * sigmoidf(acc);
    }
}

// ---------------- dt projection + bias + softplus: transposed smem (64-row tiles) ----------------
__global__ void k_dts(const float* __restrict__ dtw, const float* __restrict__ dtb){
    __shared__ float sct[Rr][66];
    int l0 = blockIdx.x * 64;
    int k = blockIdx.y, b = blockIdx.z;
    int t = threadIdx.x;
    int d = t;
    size_t bkL = (size_t)(b*Kk + k) * Ll;
    const float* cbase = g_c176 + (size_t)b * Ll * 176 + k * 44;

    // prologue: weights/bias (inputs)
    ull w2[Rr];
    #pragma unroll
    for (int r = 0; r < Rr; r++){
        float wv = dtw[((size_t)k*DI + d) * Rr + r];
        w2[r] = pk2(wv, wv);
    }
    float bias = dtb[k*DI + d];
    ull bias2 = pk2(bias, bias);

    cudaGridDependencySynchronize();
    for (int i = t; i < 64*Rr; i += 384){
        int row = i / Rr, col = i - row * Rr;
        sct[col][row] = cbase[(size_t)loc_of(k, l0 + row) * 176 + col];
    }
    __syncthreads();

    float* dp = g_dts + (bkL + l0) * DI + d;
    #pragma unroll 4
    for (int lp = 0; lp < 32; lp++){
        ull acc = bias2;
        #pragma unroll
        for (int r = 0; r < Rr; r++){
            ull cpair = *(const ull*)&sct[r][2*lp];
            acc = fma2(w2[r], cpair, acc);
        }
        float a0, a1; upk2(acc, a0, a1);
        dp[(size_t)(2*lp)   * DI] = softplus_fast(a0);
        dp[(size_t)(2*lp+1) * DI] = softplus_fast(a1);
    }
}

// ---------------- scan position iterator ----------------
struct PosIter {
    int k, p, hh, ww;
    __device__ __forceinline__ void init(int k_, int l0){
        k = k_;
        if (k == 0){ p = l0; }
        else if (k == 2){ p = Ll - 1 - l0; }
        else {
            int l2 = (k == 1) ? l0 : (Ll - 1 - l0);
            ww = l2 / Ww; hh = l2 - ww * Ww; p = hh * Ww + ww;
        }
    }
    __device__ __forceinline__ void next(){
        if (k == 0) p++;
        else if (k == 2) p--;
        else if (k == 1){
            hh++; if (hh == Hh){ hh = 0; ww++; }
            p = hh * Ww + ww;
        } else {
            hh--; if (hh < 0){ hh = Hh - 1; ww--; }
            p = hh * Ww + ww;
        }
    }
};

// geo check without keeping A2[] live
__device__ __forceinline__ bool geo_check(const float* Ar, float& A1){
    A1 = -expf(Ar[0]) * LOG2E;
    bool geo = (A1 != 0.f);
    #pragma unroll
    for (int n = 1; n < Ns; n++){
        float an = -expf(Ar[n]) * LOG2E;
        geo = geo && (fabsf(an - (float)(n+1)*A1) <= 1e-4f * fabsf(an));
    }
    return geo;
}

// ---------------- selective scan, chunked ----------------
// last chunk's summary is never consumed: those blocks exit immediately.
__global__ void __launch_bounds__(DI, 2) k_scanA(const float* __restrict__ A_logs){
    int blk = blockIdx.x;
    int chunk = blk % NCHUNK;
    if (chunk == NCHUNK - 1) return;
    int bk = blk / NCHUNK;
    int k = bk & 3, b = bk >> 2;
    int d = threadIdx.x;

    const float* Ar = A_logs + (size_t)(k*DI + d) * Ns;
    float A1;
    bool geo = geo_check(Ar, A1);      // input-only prologue
    cudaGridDependencySynchronize();

    int l0 = chunk * CLEN;
    size_t bkL = (size_t)bk * Ll;
    const float* dtp = g_dts + (bkL + l0) * DI + d;
    const float* xcb = g_xc + (size_t)b * Ll * DI + d;
    const float* cbase = g_c176 + (size_t)b * Ll * 176 + k * 44;
    size_t o = ((size_t)blk * DI + d) * Ns;

    PosIter it; it.init(k, l0);

    if (geo){
        float rp = 1.f;
        ull h2[8] = {};
        for (int s = 0; s < CLEN; s++){
            int p = it.p;
            float delta = dtp[0];
            float u = __ldg(xcb + (size_t)p * DI);
            float du = delta * u;
            float r = ex2f(delta * A1);
            ull pw[8]; powers16p(r, pw);
            const float* cp = cbase + (size_t)p * 176;
            ulonglong2 bA = *(const ulonglong2*)(cp + 12);
            ulonglong2 bB = *(const ulonglong2*)(cp + 16);
            ulonglong2 bC = *(const ulonglong2*)(cp + 20);
            ulonglong2 bD = *(const ulonglong2*)(cp + 24);
            ull dup = pk2(du, du);
            h2[0] = fma2(pw[0], h2[0], mul2(dup, bA.x));
            h2[1] = fma2(pw[1], h2[1], mul2(dup, bA.y));
            h2[2] = fma2(pw[2], h2[2], mul2(dup, bB.x));
            h2[3] = fma2(pw[3], h2[3], mul2(dup, bB.y));
            h2[4] = fma2(pw[4], h2[4], mul2(dup, bC.x));
            h2[5] = fma2(pw[5], h2[5], mul2(dup, bC.y));
            h2[6] = fma2(pw[6], h2[6], mul2(dup, bD.x));
            h2[7] = fma2(pw[7], h2[7], mul2(dup, bD.y));
            rp *= r;
            dtp += DI;
            it.next();
        }
        ull ap2[8]; powers16p(rp, ap2);
        ulonglong2* he = (ulonglong2*)(g_hend + o);
        ulonglong2* av = (ulonglong2*)(g_aprod + o);
        #pragma unroll
        for (int q = 0; q < 4; q++){
            ulonglong2 v1; v1.x = h2[2*q]; v1.y = h2[2*q+1]; he[q] = v1;
            ulonglong2 v2; v2.x = ap2[2*q]; v2.y = ap2[2*q+1]; av[q] = v2;
        }
    } else {
        float A2[Ns];
        #pragma unroll
        for (int n = 0; n < Ns; n++) A2[n] = -expf(Ar[n]) * LOG2E;
        float h[Ns], ap[Ns];
        #pragma unroll
        for (int n = 0; n < Ns; n++){ h[n] = 0.f; ap[n] = 1.f; }
        for (int s = 0; s < CLEN; s++){
            int p = it.p;
            float delta = dtp[0];
            float u = __ldg(xcb + (size_t)p * DI);
            float du = delta * u;
            const float* cp = cbase + (size_t)p * 176;
            float Bv[Ns];
            *(float4*)&Bv[0]  = *(const float4*)(cp + 12);
            *(float4*)&Bv[4]  = *(const float4*)(cp + 16);
            *(float4*)&Bv[8]  = *(const float4*)(cp + 20);
            *(float4*)&Bv[12] = *(const float4*)(cp + 24);
            #pragma unroll
            for (int n = 0; n < Ns; n++){
                float dA = ex2f(delta * A2[n]);
                h[n] = fmaf(dA, h[n], du * Bv[n]);
                ap[n] *= dA;
            }
            dtp += DI;
            it.next();
        }
        float4* he = (float4*)(g_hend + o);
        float4* av = (float4*)(g_aprod + o);
        #pragma unroll
        for (int q = 0; q < 4; q++){
            he[q] = make_float4(h[4*q], h[4*q+1], h[4*q+2], h[4*q+3]);
            av[q] = make_float4(ap[4*q], ap[4*q+1], ap[4*q+2], ap[4*q+3]);
        }
    }
}

// pass B: sequential scan over chunks -> h_init per chunk (does not touch dead last summary)
__global__ void k_scanB(){
    cudaGridDependencySynchronize();
    int gid = blockIdx.x * blockDim.x + threadIdx.x;
    int dn = gid % (DI*Ns);
    int bk = gid / (DI*Ns);
    size_t base = (size_t)bk * NCHUNK * DI * Ns + dn;
    float hr = 0.f;
    #pragma unroll 4
    for (int c = 0; c < NCHUNK - 1; c++){
        size_t idx = base + (size_t)c * DI * Ns;
        g_hinit[idx] = hr;
        hr = g_aprod[idx] * hr + g_hend[idx];
    }
    g_hinit[base + (size_t)(NCHUNK-1) * DI * Ns] = hr;
}

// pass C: replay with correct h_init, write y at RASTER position
__global__ void __launch_bounds__(DI, 2) k_scanC(const float* __restrict__ A_logs,
                                                 const float* __restrict__ Ds){
    int blk = blockIdx.x;
    int chunk = blk % NCHUNK;
    int bk = blk / NCHUNK;
    int k = bk & 3, b = bk >> 2;
    int d = threadIdx.x;

    const float* Ar = A_logs + (size_t)(k*DI + d) * Ns;
    float A1;
    bool geo = geo_check(Ar, A1);      // input-only prologue
    float Dv = Ds[k*DI + d];
    cudaGridDependencySynchronize();

    int l0 = chunk * CLEN;
    size_t bkL = (size_t)bk * Ll;
    const float* dtp = g_dts + (bkL + l0) * DI + d;
    const float* xcb = g_xc + (size_t)b * Ll * DI + d;
    const float* cbase = g_c176 + (size_t)b * Ll * 176 + k * 44;
    float* ybase = g_y + bkL * DI + d;
    size_t o = ((size_t)blk * DI + d) * Ns;

    PosIter it; it.init(k, l0);

    if (geo){
        ull h2[8];
        {
            const ulonglong2* hi = (const ulonglong2*)(g_hinit + o);
            #pragma unroll
            for (int q = 0; q < 4; q++){ ulonglong2 v = hi[q]; h2[2*q] = v.x; h2[2*q+1] = v.y; }
        }
        for (int s = 0; s < CLEN; s++){
            int p = it.p;
            float delta = dtp[0];
            float u = __ldg(xcb + (size_t)p * DI);
            float du = delta * u;
            float r = ex2f(delta * A1);
            ull pw[8]; powers16p(r, pw);
            const float* cp = cbase + (size_t)p * 176;
            ulonglong2 bA = *(const ulonglong2*)(cp + 12);
            ulonglong2 bB = *(const ulonglong2*)(cp + 16);
            ulonglong2 bC = *(const ulonglong2*)(cp + 20);
            ulonglong2 bD = *(const ulonglong2*)(cp + 24);
            ulonglong2 cA = *(const ulonglong2*)(cp + 28);
            ulonglong2 cB = *(const ulonglong2*)(cp + 32);
            ulonglong2 cC = *(const ulonglong2*)(cp + 36);
            ulonglong2 cD = *(const ulonglong2*)(cp + 40);
            ull dup = pk2(du, du);
            h2[0] = fma2(pw[0], h2[0], mul2(dup, bA.x));
            h2[1] = fma2(pw[1], h2[1], mul2(dup, bA.y));
            h2[2] = fma2(pw[2], h2[2], mul2(dup, bB.x));
            h2[3] = fma2(pw[3], h2[3], mul2(dup, bB.y));
            h2[4] = fma2(pw[4], h2[4], mul2(dup, bC.x));
            h2[5] = fma2(pw[5], h2[5], mul2(dup, bC.y));
            h2[6] = fma2(pw[6], h2[6], mul2(dup, bD.x));
            h2[7] = fma2(pw[7], h2[7], mul2(dup, bD.y));
            ull acc2 = mul2(h2[0], cA.x);
            acc2 = fma2(h2[1], cA.y, acc2);
            acc2 = fma2(h2[2], cB.x, acc2);
            acc2 = fma2(h2[3], cB.y, acc2);
            acc2 = fma2(h2[4], cC.x, acc2);
            acc2 = fma2(h2[5], cC.y, acc2);
            acc2 = fma2(h2[6], cD.x, acc2);
            acc2 = fma2(h2[7], cD.y, acc2);
            float alo, ahi; upk2(acc2, alo, ahi);
            ybase[(size_t)p * DI] = fmaf(Dv, u, alo + ahi);
            dtp += DI;
            it.next();
        }
    } else {
        float A2[Ns];
        #pragma unroll
        for (int n = 0; n < Ns; n++) A2[n] = -expf(Ar[n]) * LOG2E;
        float h[Ns];
        {
            const float4* hi = (const float4*)(g_hinit + o);
            #pragma unroll
            for (int q = 0; q < 4; q++){
                float4 v = hi[q];
                h[4*q] = v.x; h[4*q+1] = v.y; h[4*q+2] = v.z; h[4*q+3] = v.w;
            }
        }
        for (int s = 0; s < CLEN; s++){
            int p = it.p;
            float delta = dtp[0];
            float u = __ldg(xcb + (size_t)p * DI);
            float du = delta * u;
            const float* cp = cbase + (size_t)p * 176;
            float acc = 0.f;
            #pragma unroll
            for (int q = 0; q < 4; q++){
                float4 bq = *(const float4*)(cp + 12 + 4*q);
                float4 cq = *(const float4*)(cp + 28 + 4*q);
                float dA0 = ex2f(delta * A2[4*q+0]);
                float dA1 = ex2f(delta * A2[4*q+1]);
                float dA2 = ex2f(delta * A2[4*q+2]);
                float dA3 = ex2f(delta * A2[4*q+3]);
                h[4*q+0] = fmaf(dA0, h[4*q+0], du * bq.x); acc = fmaf(h[4*q+0], cq.x, acc);
                h[4*q+1] = fmaf(dA1, h[4*q+1], du * bq.y); acc = fmaf(h[4*q+1], cq.y, acc);
                h[4*q+2] = fmaf(dA2, h[4*q+2], du * bq.z); acc = fmaf(h[4*q+2], cq.z, acc);
                h[4*q+3] = fmaf(dA3, h[4*q+3], du * bq.w); acc = fmaf(h[4*q+3], cq.w, acc);
            }
            ybase[(size_t)p * DI] = fmaf(Dv, u, acc);
            dtp += DI;
            it.next();
        }
    }
}

// ---------------- merge 4 directions + LayerNorm + gate; also zeroes d_out ----------------
__global__ void k_ln(const float* __restrict__ gam, const float* __restrict__ bet,
                     float* __restrict__ out, int out_n){
    int t = threadIdx.x;
    {
        int nt = gridDim.x * 128;
        int gid = blockIdx.x * 128 + t;
        for (int i = gid; i < out_n; i += nt) out[i] = 0.f;
    }
    float gm[3], bt[3];
    #pragma unroll
    for (int j = 0; j < 3; j++){ gm[j] = gam[t + j*128]; bt[j] = bet[t + j*128]; }
    cudaGridDependencySynchronize();

    int p = blockIdx.x % Ll;
    int b = blockIdx.x / Ll;
    const float* y0 = g_y + (((size_t)(b*Kk + 0) * Ll) + p) * DI;
    const float* y1 = y0 + (size_t)Ll * DI;
    const float* y2 = y1 + (size_t)Ll * DI;
    const float* y3 = y2 + (size_t)Ll * DI;
    float v[3];
    float s1 = 0.f, s2 = 0.f;
    #pragma unroll
    for (int j = 0; j < 3; j++){
        int d = t + j * 128;
        float y = y0[d] + y1[d] + y2[d] + y3[d];
        v[j] = y; s1 += y; s2 += y*y;
    }
    #pragma unroll
    for (int off = 16; off > 0; off >>= 1){
        s1 += __shfl_xor_sync(0xffffffffu, s1, off);
        s2 += __shfl_xor_sync(0xffffffffu, s2, off);
    }
    __shared__ float r1[4], r2[4];
    int warp = t >> 5, lane = t & 31;
    if (lane == 0){ r1[warp] = s1; r2[warp] = s2; }
    __syncthreads();
    float S1 = r1[0] + r1[1] + r1[2] + r1[3];
    float S2 = r2[0] + r2[1] + r2[2] + r2[3];
    float mu = S1 * (1.f / DI);
    float var = S2 * (1.f / DI) - mu * mu;
    float rstd = rsqrtf(var + 1e-5f);
    const float* zrow = g_xz + ((size_t)b*Ll + p) * (2*DI) + DI;
    float* grow = g_g + ((size_t)b*Ll + p) * DI;
    #pragma unroll
    for (int j = 0; j < 3; j++){
        int d = t + j * 128;
        float zn = zrow[d];
        float gate = zn * sigmoidf(zn);
        grow[d] = ((v[j] - mu) * rstd * gm[j] + bt[j]) * gate;
    }
}

// ---------------- launch (PDL chain, implicit triggers) ----------------
template<typename K, typename... Args>
static inline void launch_pdl(K kern, dim3 g, dim3 b, Args... args){
    cudaLaunchConfig_t cfg = {};
    cfg.gridDim = g; cfg.blockDim = b; cfg.dynamicSmemBytes = 0; cfg.stream = 0;
    cudaLaunchAttribute attr[1];
    attr[0].id = cudaLaunchAttributeProgrammaticStreamSerialization;
    attr[0].val.programmaticStreamSerializationAllowed = 1;
    cfg.attrs = attr; cfg.numAttrs = 1;
    cudaLaunchKernelEx(&cfg, kern, args...);
}

extern "C" void kernel_launch(void* const* d_in, const int* in_sizes, int n_in,
                              void* d_out, int out_size){
    const float* x      = (const float*)d_in[0];
    const float* in_w   = (const float*)d_in[1];
    const float* conv_w = (const float*)d_in[2];
    const float* conv_b = (const float*)d_in[3];
    const float* xproj  = (const float*)d_in[4];
    const float* dtw    = (const float*)d_in[5];
    const float* dtb    = (const float*)d_in[6];
    const float* Alog   = (const float*)d_in[7];
    const float* Ds     = (const float*)d_in[8];
    const float* gam    = (const float*)d_in[9];
    const float* bet    = (const float*)d_in[10];
    const float* outw   = (const float*)d_in[11];
    float* out = (float*)d_out;

    k_inproj <<<dim3((2*DI)/64, (Bb*Ll)/64), 256>>>(x, in_w);
    launch_pdl(k_conv,    dim3(Bb*Ll), dim3(128), conv_w, conv_b);
    launch_pdl(k_cproj,   dim3(3, (Bb*Ll)/64, 2), dim3(256), xproj);
    launch_pdl(k_dts,     dim3(Ll/64, Kk, Bb), dim3(DI), dtw, dtb);
    launch_pdl(k_scanA,   dim3(Bb*Kk*NCHUNK), dim3(DI), Alog);
    launch_pdl(k_scanB,   dim3((Bb*Kk*DI*Ns)/256), dim3(256));
    launch_pdl(k_scanC,   dim3(Bb*Kk*NCHUNK), dim3(DI), Alog, Ds);
    launch_pdl(k_ln,      dim3(Bb*Ll), dim3(128), gam, bet, out, out_size);
    launch_pdl(k_outproj, dim3(DMo/64, (Bb*Ll)/64, 2), dim3(256), outw, out);
}

// round 17
// speedup vs baseline: 1.0521x; 1.0312x over previous
#include <cuda_runtime.h>
#include <cstdint>

typedef unsigned long long ull;

#define Bb 2
#define Hh 48
#define Ww 48
#define DMo 192
#define Ns 16
#define DI 384
#define Rr 12
#define Kk 4
#define Ll (Hh*Ww)          // 2304
#define NCHUNK 36
#define CLEN (Ll/NCHUNK)    // 64
#define LOG2E 1.4426950408889634f
#define LN2 0.6931471805599453f

// ---------------- static device scratch ----------------
__device__ float g_xz  [(size_t)Bb*Ll*(2*DI)];
__device__ float g_xc  [(size_t)Bb*Ll*DI];
__device__ float g_c176[(size_t)Bb*Ll*176];
__device__ float g_dts [(size_t)Bb*Kk*Ll*DI];
__device__ float g_ysum[(size_t)Bb*Ll*DI];          // direction-summed scan output (b,p,d)
__device__ float g_g   [(size_t)Bb*Ll*DI];
__device__ float g_hend [(size_t)Bb*Kk*NCHUNK*DI*Ns];
__device__ float g_aprod[(size_t)Bb*Kk*NCHUNK*DI*Ns];
__device__ float g_hinit[(size_t)Bb*Kk*NCHUNK*DI*Ns];

// ---------------- helpers ----------------
__device__ __forceinline__ float ex2f(float x){ float y; asm("ex2.approx.f32 %0, %1;" : "=f"(y) : "f"(x)); return y; }
__device__ __forceinline__ float lg2f(float x){ float y; asm("lg2.approx.f32 %0, %1;" : "=f"(y) : "f"(x)); return y; }

__device__ __forceinline__ float softplus_fast(float x){
    float e = ex2f(-fabsf(x) * LOG2E);
    return fmaxf(x, 0.f) + LN2 * lg2f(1.f + e);
}
__device__ __forceinline__ float sigmoidf(float x){
    return 1.f / (1.f + __expf(-x));
}

__device__ __forceinline__ ull pk2(float lo, float hi){
    ull r; asm("mov.b64 %0, {%1, %2};" : "=l"(r) : "r"(__float_as_uint(lo)), "r"(__float_as_uint(hi)));
    return r;
}
__device__ __forceinline__ void upk2(ull v, float& lo, float& hi){
    unsigned a, b; asm("mov.b64 {%0, %1}, %2;" : "=r"(a), "=r"(b) : "l"(v));
    lo = __uint_as_float(a); hi = __uint_as_float(b);
}
__device__ __forceinline__ ull fma2(ull a, ull b, ull c){
    ull d; asm("fma.rn.f32x2 %0, %1, %2, %3;" : "=l"(d) : "l"(a), "l"(b), "l"(c));
    return d;
}
__device__ __forceinline__ ull mul2(ull a, ull b){
    ull d; asm("mul.rn.f32x2 %0, %1, %2;" : "=l"(d) : "l"(a), "l"(b));
    return d;
}

// pair powers: p[i] = (r^(2i+1), r^(2i+2)), squaring tree (depth ~3)
__device__ __forceinline__ void powers16p(float r, ull* p){
    float r2 = r*r, r4 = r2*r2, r8 = r4*r4;
    ull R2 = pk2(r2, r2), R4 = pk2(r4, r4), R8 = pk2(r8, r8);
    p[0] = pk2(r, r2);
    p[1] = mul2(p[0], R2);
    p[2] = mul2(p[0], R4);
    p[3] = mul2(p[1], R4);
    p[4] = mul2(p[0], R8);
    p[5] = mul2(p[1], R8);
    p[6] = mul2(p[2], R8);
    p[7] = mul2(p[3], R8);
}

// raster location visited at scan step l of direction k (involution)
__device__ __forceinline__ int loc_of(int k, int l){
    int l2 = (k >= 2) ? (Ll - 1 - l) : l;
    if (k & 1){ int w = l2 / Ww; int h = l2 - w * Ww; return h * Ww + w; }
    return l2;
}

// ---------------- NT GEMM, pair-over-K FFMA2 micro, optional split-K ----------------
template<int SPLITS, bool ATOMIC, bool DEP>
__device__ __forceinline__ void gemm_nt2(const float* __restrict__ A, const float* __restrict__ B,
                                         float* __restrict__ C, int K, int Nrow){
    __shared__ float As[64][20];
    __shared__ float Bs[8][132];
    int t  = threadIdx.x;
    int tx = t & 15, ty = t >> 4;
    int m0 = blockIdx.y * 64, n0 = blockIdx.x * 64;
    int klen = K / SPLITS;
    int kbeg = klen * blockIdx.z;
    ull acc[4][4] = {};
    int r  = t >> 2;
    int kc = (t & 3) << 2;
    int brow = n0 + r; if (brow >= Nrow) brow = Nrow - 1;
    const float* Ap = A + (size_t)(m0 + r) * K + kbeg + kc;
    const float* Bp = B + (size_t)brow * K + kbeg + kc;
    float4 bv = *(const float4*)Bp;      // weights: input tensor, dependency-free
    if (DEP) cudaGridDependencySynchronize();
    float4 av = *(const float4*)Ap;
    for (int k0 = 0; k0 < klen; k0 += 16){
        *(float4*)&As[r][kc] = av;
        *(ull*)&Bs[(kc>>1)+0][2*r] = pk2(bv.x, bv.y);
        *(ull*)&Bs[(kc>>1)+1][2*r] = pk2(bv.z, bv.w);
        __syncthreads();
        if (k0 + 16 < klen){
            av = *(const float4*)(Ap + k0 + 16);
            bv = *(const float4*)(Bp + k0 + 16);
        }
        #pragma unroll
        for (int kp = 0; kp < 8; kp++){
            ull a0 = *(const ull*)&As[(ty<<2)+0][kp<<1];
            ull a1 = *(const ull*)&As[(ty<<2)+1][kp<<1];
            ull a2 = *(const ull*)&As[(ty<<2)+2][kp<<1];
            ull a3 = *(const ull*)&As[(ty<<2)+3][kp<<1];
            ull b0 = *(const ull*)&Bs[kp][2*tx];
            ull b1 = *(const ull*)&Bs[kp][2*(tx+16)];
            ull b2 = *(const ull*)&Bs[kp][2*(tx+32)];
            ull b3 = *(const ull*)&Bs[kp][2*(tx+48)];
            acc[0][0]=fma2(a0,b0,acc[0][0]); acc[0][1]=fma2(a0,b1,acc[0][1]);
            acc[0][2]=fma2(a0,b2,acc[0][2]); acc[0][3]=fma2(a0,b3,acc[0][3]);
            acc[1][0]=fma2(a1,b0,acc[1][0]); acc[1][1]=fma2(a1,b1,acc[1][1]);
            acc[1][2]=fma2(a1,b2,acc[1][2]); acc[1][3]=fma2(a1,b3,acc[1][3]);
            acc[2][0]=fma2(a2,b0,acc[2][0]); acc[2][1]=fma2(a2,b1,acc[2][1]);
            acc[2][2]=fma2(a2,b2,acc[2][2]); acc[2][3]=fma2(a2,b3,acc[2][3]);
            acc[3][0]=fma2(a3,b0,acc[3][0]); acc[3][1]=fma2(a3,b1,acc[3][1]);
            acc[3][2]=fma2(a3,b2,acc[3][2]); acc[3][3]=fma2(a3,b3,acc[3][3]);
        }
        __syncthreads();
    }
    #pragma unroll
    for (int i = 0; i < 4; i++){
        int m = m0 + (ty<<2) + i;
        #pragma unroll
        for (int j = 0; j < 4; j++){
            int n = n0 + tx + 16*j;
            if (n < Nrow){
                float lo, hi; upk2(acc[i][j], lo, hi);
                if (ATOMIC) atomicAdd(&C[(size_t)m * Nrow + n], lo + hi);
                else        C[(size_t)m * Nrow + n] = lo + hi;
            }
        }
    }
}

// k_inproj also zeroes g_c176 (split-K accumulation target of k_cproj)
__global__ void __launch_bounds__(256, 3) k_inproj(const float* __restrict__ x, const float* __restrict__ w){
    {
        size_t nt = (size_t)gridDim.x * gridDim.y * 256;
        size_t gid = ((size_t)blockIdx.y * gridDim.x + blockIdx.x) * 256 + threadIdx.x;
        const size_t n4 = (size_t)Bb*Ll*176/4;
        float4 z = make_float4(0.f,0.f,0.f,0.f);
        for (size_t i = gid; i < n4; i += nt) ((float4*)g_c176)[i] = z;
    }
    gemm_nt2<1, false, false>(x, w, g_xz, DMo, 2*DI);
}
__global__ void __launch_bounds__(256, 3) k_outproj(const float* __restrict__ w, float* __restrict__ out){
    gemm_nt2<2, true, true>(g_g, w, out, DI, DMo);
}
__global__ void __launch_bounds__(256, 3) k_cproj(const float* __restrict__ xproj){
    gemm_nt2<2, true, true>(g_xc, xproj, g_c176, DI, 176);
}

// ---------------- depthwise conv 3x3 + bias + SiLU (channel-last) ----------------
__global__ void k_conv(const float* __restrict__ cw, const float* __restrict__ cb){
    int p = blockIdx.x % Ll;
    int b = blockIdx.x / Ll;
    int h = p / Ww, w = p % Ww;
    float biasv[3]; float wreg[3][9];
    #pragma unroll
    for (int j = 0; j < 3; j++){
        int d = threadIdx.x + j * 128;
        biasv[j] = cb[d];
        #pragma unroll
        for (int q = 0; q < 9; q++) wreg[j][q] = cw[d * 9 + q];
    }
    cudaGridDependencySynchronize();
    const float* base = g_xz + (size_t)b * Ll * (2*DI);
    #pragma unroll
    for (int j = 0; j < 3; j++){
        int d = threadIdx.x + j * 128;
        float acc = biasv[j];
        #pragma unroll
        for (int dh = -1; dh <= 1; dh++){
            int hh = h + dh;
            if ((unsigned)hh >= (unsigned)Hh) continue;
            #pragma unroll
            for (int dw = -1; dw <= 1; dw++){
                int ww2 = w + dw;
                if ((unsigned)ww2 >= (unsigned)Ww) continue;
                acc = fmaf(base[(size_t)(hh*Ww + ww2) * (2*DI) + d], wreg[j][(dh+1)*3 + (dw+1)], acc);
            }
        }
        g_xc[((size_t)b*Ll + p) * DI + d] = acc * sigmoidf(acc);
    }
}

// ---------------- dt projection + bias + softplus; also zeroes g_ysum (scanC's accumulator) ----------------
__global__ void k_dts(const float* __restrict__ dtw, const float* __restrict__ dtb){
    __shared__ float sct[Rr][66];
    int l0 = blockIdx.x * 64;
    int k = blockIdx.y, b = blockIdx.z;
    int t = threadIdx.x;
    int d = t;
    size_t bkL = (size_t)(b*Kk + k) * Ll;
    const float* cbase = g_c176 + (size_t)b * Ll * 176 + k * 44;

    // dependency-free prologue: zero g_ysum slice + load weights/bias (inputs)
    {
        size_t nt = (size_t)gridDim.x * gridDim.y * gridDim.z * 384;
        size_t gid = ((size_t)(blockIdx.z * gridDim.y + blockIdx.y) * gridDim.x + blockIdx.x) * 384 + t;
        const size_t n4 = (size_t)Bb*Ll*DI/4;
        float4 z = make_float4(0.f,0.f,0.f,0.f);
        for (size_t i = gid; i < n4; i += nt) ((float4*)g_ysum)[i] = z;
    }
    ull w2[Rr];
    #pragma unroll
    for (int r = 0; r < Rr; r++){
        float wv = dtw[((size_t)k*DI + d) * Rr + r];
        w2[r] = pk2(wv, wv);
    }
    float bias = dtb[k*DI + d];
    ull bias2 = pk2(bias, bias);

    cudaGridDependencySynchronize();
    for (int i = t; i < 64*Rr; i += 384){
        int row = i / Rr, col = i - row * Rr;
        sct[col][row] = cbase[(size_t)loc_of(k, l0 + row) * 176 + col];
    }
    __syncthreads();

    float* dp = g_dts + (bkL + l0) * DI + d;
    #pragma unroll 4
    for (int lp = 0; lp < 32; lp++){
        ull acc = bias2;
        #pragma unroll
        for (int r = 0; r < Rr; r++){
            ull cpair = *(const ull*)&sct[r][2*lp];
            acc = fma2(w2[r], cpair, acc);
        }
        float a0, a1; upk2(acc, a0, a1);
        dp[(size_t)(2*lp)   * DI] = softplus_fast(a0);
        dp[(size_t)(2*lp+1) * DI] = softplus_fast(a1);
    }
}

// ---------------- scan position iterator ----------------
struct PosIter {
    int k, p, hh, ww;
    __device__ __forceinline__ void init(int k_, int l0){
        k = k_;
        if (k == 0){ p = l0; }
        else if (k == 2){ p = Ll - 1 - l0; }
        else {
            int l2 = (k == 1) ? l0 : (Ll - 1 - l0);
            ww = l2 / Ww; hh = l2 - ww * Ww; p = hh * Ww + ww;
        }
    }
    __device__ __forceinline__ void next(){
        if (k == 0) p++;
        else if (k == 2) p--;
        else if (k == 1){
            hh++; if (hh == Hh){ hh = 0; ww++; }
            p = hh * Ww + ww;
        } else {
            hh--; if (hh < 0){ hh = Hh - 1; ww--; }
            p = hh * Ww + ww;
        }
    }
};

// geo check without keeping A2[] live
__device__ __forceinline__ bool geo_check(const float* Ar, float& A1){
    A1 = -expf(Ar[0]) * LOG2E;
    bool geo = (A1 != 0.f);
    #pragma unroll
    for (int n = 1; n < Ns; n++){
        float an = -expf(Ar[n]) * LOG2E;
        geo = geo && (fabsf(an - (float)(n+1)*A1) <= 1e-4f * fabsf(an));
    }
    return geo;
}

// ---------------- selective scan, chunked ----------------
// last chunk's summary is never consumed: those blocks exit immediately.
__global__ void __launch_bounds__(DI, 2) k_scanA(const float* __restrict__ A_logs){
    int blk = blockIdx.x;
    int chunk = blk % NCHUNK;
    if (chunk == NCHUNK - 1) return;
    int bk = blk / NCHUNK;
    int k = bk & 3, b = bk >> 2;
    int d = threadIdx.x;

    const float* Ar = A_logs + (size_t)(k*DI + d) * Ns;
    float A1;
    bool geo = geo_check(Ar, A1);      // input-only prologue
    cudaGridDependencySynchronize();

    int l0 = chunk * CLEN;
    size_t bkL = (size_t)bk * Ll;
    const float* dtp = g_dts + (bkL + l0) * DI + d;
    const float* xcb = g_xc + (size_t)b * Ll * DI + d;
    const float* cbase = g_c176 + (size_t)b * Ll * 176 + k * 44;
    size_t o = ((size_t)blk * DI + d) * Ns;

    PosIter it; it.init(k, l0);

    if (geo){
        float rp = 1.f;
        ull h2[8] = {};
        for (int s = 0; s < CLEN; s++){
            int p = it.p;
            float delta = dtp[0];
            float u = __ldg(xcb + (size_t)p * DI);
            float du = delta * u;
            float r = ex2f(delta * A1);
            ull pw[8]; powers16p(r, pw);
            const float* cp = cbase + (size_t)p * 176;
            ulonglong2 bA = *(const ulonglong2*)(cp + 12);
            ulonglong2 bB = *(const ulonglong2*)(cp + 16);
            ulonglong2 bC = *(const ulonglong2*)(cp + 20);
            ulonglong2 bD = *(const ulonglong2*)(cp + 24);
            ull dup = pk2(du, du);
            h2[0] = fma2(pw[0], h2[0], mul2(dup, bA.x));
            h2[1] = fma2(pw[1], h2[1], mul2(dup, bA.y));
            h2[2] = fma2(pw[2], h2[2], mul2(dup, bB.x));
            h2[3] = fma2(pw[3], h2[3], mul2(dup, bB.y));
            h2[4] = fma2(pw[4], h2[4], mul2(dup, bC.x));
            h2[5] = fma2(pw[5], h2[5], mul2(dup, bC.y));
            h2[6] = fma2(pw[6], h2[6], mul2(dup, bD.x));
            h2[7] = fma2(pw[7], h2[7], mul2(dup, bD.y));
            rp *= r;
            dtp += DI;
            it.next();
        }
        ull ap2[8]; powers16p(rp, ap2);
        ulonglong2* he = (ulonglong2*)(g_hend + o);
        ulonglong2* av = (ulonglong2*)(g_aprod + o);
        #pragma unroll
        for (int q = 0; q < 4; q++){
            ulonglong2 v1; v1.x = h2[2*q]; v1.y = h2[2*q+1]; he[q] = v1;
            ulonglong2 v2; v2.x = ap2[2*q]; v2.y = ap2[2*q+1]; av[q] = v2;
        }
    } else {
        float A2[Ns];
        #pragma unroll
        for (int n = 0; n < Ns; n++) A2[n] = -expf(Ar[n]) * LOG2E;
        float h[Ns], ap[Ns];
        #pragma unroll
        for (int n = 0; n < Ns; n++){ h[n] = 0.f; ap[n] = 1.f; }
        for (int s = 0; s < CLEN; s++){
            int p = it.p;
            float delta = dtp[0];
            float u = __ldg(xcb + (size_t)p * DI);
            float du = delta * u;
            const float* cp = cbase + (size_t)p * 176;
            float Bv[Ns];
            *(float4*)&Bv[0]  = *(const float4*)(cp + 12);
            *(float4*)&Bv[4]  = *(const float4*)(cp + 16);
            *(float4*)&Bv[8]  = *(const float4*)(cp + 20);
            *(float4*)&Bv[12] = *(const float4*)(cp + 24);
            #pragma unroll
            for (int n = 0; n < Ns; n++){
                float dA = ex2f(delta * A2[n]);
                h[n] = fmaf(dA, h[n], du * Bv[n]);
                ap[n] *= dA;
            }
            dtp += DI;
            it.next();
        }
        float4* he = (float4*)(g_hend + o);
        float4* av = (float4*)(g_aprod + o);
        #pragma unroll
        for (int q = 0; q < 4; q++){
            he[q] = make_float4(h[4*q], h[4*q+1], h[4*q+2], h[4*q+3]);
            av[q] = make_float4(ap[4*q], ap[4*q+1], ap[4*q+2], ap[4*q+3]);
        }
    }
}

// pass B: sequential scan over chunks -> h_init per chunk (does not read dead last summary)
__global__ void k_scanB(){
    cudaGridDependencySynchronize();
    int gid = blockIdx.x * blockDim.x + threadIdx.x;
    int dn = gid % (DI*Ns);
    int bk = gid / (DI*Ns);
    size_t base = (size_t)bk * NCHUNK * DI * Ns + dn;
    float hr = 0.f;
    #pragma unroll 4
    for (int c = 0; c < NCHUNK - 1; c++){
        size_t idx = base + (size_t)c * DI * Ns;
        g_hinit[idx] = hr;
        hr = g_aprod[idx] * hr + g_hend[idx];
    }
    g_hinit[base + (size_t)(NCHUNK-1) * DI * Ns] = hr;
}

// pass C: replay with correct h_init, accumulate all 4 directions into g_ysum via REDG
__global__ void __launch_bounds__(DI, 2) k_scanC(const float* __restrict__ A_logs,
                                                 const float* __restrict__ Ds){
    int blk = blockIdx.x;
    int chunk = blk % NCHUNK;
    int bk = blk / NCHUNK;
    int k = bk & 3, b = bk >> 2;
    int d = threadIdx.x;

    const float* Ar = A_logs + (size_t)(k*DI + d) * Ns;
    float A1;
    bool geo = geo_check(Ar, A1);      // input-only prologue
    float Dv = Ds[k*DI + d];
    cudaGridDependencySynchronize();

    int l0 = chunk * CLEN;
    size_t bkL = (size_t)bk * Ll;
    const float* dtp = g_dts + (bkL + l0) * DI + d;
    const float* xcb = g_xc + (size_t)b * Ll * DI + d;
    const float* cbase = g_c176 + (size_t)b * Ll * 176 + k * 44;
    float* ybase = g_ysum + (size_t)b * Ll * DI + d;
    size_t o = ((size_t)blk * DI + d) * Ns;

    PosIter it; it.init(k, l0);

    if (geo){
        ull h2[8];
        {
            const ulonglong2* hi = (const ulonglong2*)(g_hinit + o);
            #pragma unroll
            for (int q = 0; q < 4; q++){ ulonglong2 v = hi[q]; h2[2*q] = v.x; h2[2*q+1] = v.y; }
        }
        for (int s = 0; s < CLEN; s++){
            int p = it.p;
            float delta = dtp[0];
            float u = __ldg(xcb + (size_t)p * DI);
            float du = delta * u;
            float r = ex2f(delta * A1);
            ull pw[8]; powers16p(r, pw);
            const float* cp = cbase + (size_t)p * 176;
            ulonglong2 bA = *(const ulonglong2*)(cp + 12);
            ulonglong2 bB = *(const ulonglong2*)(cp + 16);
            ulonglong2 bC = *(const ulonglong2*)(cp + 20);
            ulonglong2 bD = *(const ulonglong2*)(cp + 24);
            ulonglong2 cA = *(const ulonglong2*)(cp + 28);
            ulonglong2 cB = *(const ulonglong2*)(cp + 32);
            ulonglong2 cC = *(const ulonglong2*)(cp + 36);
            ulonglong2 cD = *(const ulonglong2*)(cp + 40);
            ull dup = pk2(du, du);
            h2[0] = fma2(pw[0], h2[0], mul2(dup, bA.x));
            h2[1] = fma2(pw[1], h2[1], mul2(dup, bA.y));
            h2[2] = fma2(pw[2], h2[2], mul2(dup, bB.x));
            h2[3] = fma2(pw[3], h2[3], mul2(dup, bB.y));
            h2[4] = fma2(pw[4], h2[4], mul2(dup, bC.x));
            h2[5] = fma2(pw[5], h2[5], mul2(dup, bC.y));
            h2[6] = fma2(pw[6], h2[6], mul2(dup, bD.x));
            h2[7] = fma2(pw[7], h2[7], mul2(dup, bD.y));
            ull acc2 = mul2(h2[0], cA.x);
            acc2 = fma2(h2[1], cA.y, acc2);
            acc2 = fma2(h2[2], cB.x, acc2);
            acc2 = fma2(h2[3], cB.y, acc2);
            acc2 = fma2(h2[4], cC.x, acc2);
            acc2 = fma2(h2[5], cC.y, acc2);
            acc2 = fma2(h2[6], cD.x, acc2);
            acc2 = fma2(h2[7], cD.y, acc2);
            float alo, ahi; upk2(acc2, alo, ahi);
            atomicAdd(&ybase[(size_t)p * DI], fmaf(Dv, u, alo + ahi));
            dtp += DI;
            it.next();
        }
    } else {
        float A2[Ns];
        #pragma unroll
        for (int n = 0; n < Ns; n++) A2[n] = -expf(Ar[n]) * LOG2E;
        float h[Ns];
        {
            const float4* hi = (const float4*)(g_hinit + o);
            #pragma unroll
            for (int q = 0; q < 4; q++){
                float4 v = hi[q];
                h[4*q] = v.x; h[4*q+1] = v.y; h[4*q+2] = v.z; h[4*q+3] = v.w;
            }
        }
        for (int s = 0; s < CLEN; s++){
            int p = it.p;
            float delta = dtp[0];
            float u = __ldg(xcb + (size_t)p * DI);
            float du = delta * u;
            const float* cp = cbase + (size_t)p * 176;
            float acc = 0.f;
            #pragma unroll
            for (int q = 0; q < 4; q++){
                float4 bq = *(const float4*)(cp + 12 + 4*q);
                float4 cq = *(const float4*)(cp + 28 + 4*q);
                float dA0 = ex2f(delta * A2[4*q+0]);
                float dA1 = ex2f(delta * A2[4*q+1]);
                float dA2 = ex2f(delta * A2[4*q+2]);
                float dA3 = ex2f(delta * A2[4*q+3]);
                h[4*q+0] = fmaf(dA0, h[4*q+0], du * bq.x); acc = fmaf(h[4*q+0], cq.x, acc);
                h[4*q+1] = fmaf(dA1, h[4*q+1], du * bq.y); acc = fmaf(h[4*q+1], cq.y, acc);
                h[4*q+2] = fmaf(dA2, h[4*q+2], du * bq.z); acc = fmaf(h[4*q+2], cq.z, acc);
                h[4*q+3] = fmaf(dA3, h[4*q+3], du * bq.w); acc = fmaf(h[4*q+3], cq.w, acc);
            }
            atomicAdd(&ybase[(size_t)p * DI], fmaf(Dv, u, acc));
            dtp += DI;
            it.next();
        }
    }
}

// ---------------- LayerNorm + gate over direction-summed y; also zeroes d_out ----------------
__global__ void k_ln(const float* __restrict__ gam, const float* __restrict__ bet,
                     float* __restrict__ out, int out_n){
    int t = threadIdx.x;
    {
        int nt = gridDim.x * 128;
        int gid = blockIdx.x * 128 + t;
        for (int i = gid; i < out_n; i += nt) out[i] = 0.f;
    }
    float gm[3], bt[3];
    #pragma unroll
    for (int j = 0; j < 3; j++){ gm[j] = gam[t + j*128]; bt[j] = bet[t + j*128]; }
    cudaGridDependencySynchronize();

    int p = blockIdx.x % Ll;
    int b = blockIdx.x / Ll;
    const float* yrow = g_ysum + ((size_t)b*Ll + p) * DI;
    float v[3];
    float s1 = 0.f, s2 = 0.f;
    #pragma unroll
    for (int j = 0; j < 3; j++){
        int d = t + j * 128;
        float y = yrow[d];
        v[j] = y; s1 += y; s2 += y*y;
    }
    #pragma unroll
    for (int off = 16; off > 0; off >>= 1){
        s1 += __shfl_xor_sync(0xffffffffu, s1, off);
        s2 += __shfl_xor_sync(0xffffffffu, s2, off);
    }
    __shared__ float r1[4], r2[4];
    int warp = t >> 5, lane = t & 31;
    if (lane == 0){ r1[warp] = s1; r2[warp] = s2; }
    __syncthreads();
    float S1 = r1[0] + r1[1] + r1[2] + r1[3];
    float S2 = r2[0] + r2[1] + r2[2] + r2[3];
    float mu = S1 * (1.f / DI);
    float var = S2 * (1.f / DI) - mu * mu;
    float rstd = rsqrtf(var + 1e-5f);
    const float* zrow = g_xz + ((size_t)b*Ll + p) * (2*DI) + DI;
    float* grow = g_g + ((size_t)b*Ll + p) * DI;
    #pragma unroll
    for (int j = 0; j < 3; j++){
        int d = t + j * 128;
        float zn = zrow[d];
        float gate = zn * sigmoidf(zn);
        grow[d] = ((v[j] - mu) * rstd * gm[j] + bt[j]) * gate;
    }
}

// ---------------- launch (PDL chain, implicit triggers) ----------------
template<typename K, typename... Args>
static inline void launch_pdl(K kern, dim3 g, dim3 b, Args... args){
    cudaLaunchConfig_t cfg = {};
    cfg.gridDim = g; cfg.blockDim = b; cfg.dynamicSmemBytes = 0; cfg.stream = 0;
    cudaLaunchAttribute attr[1];
    attr[0].id = cudaLaunchAttributeProgrammaticStreamSerialization;
    attr[0].val.programmaticStreamSerializationAllowed = 1;
    cfg.attrs = attr; cfg.numAttrs = 1;
    cudaLaunchKernelEx(&cfg, kern, args...);
}

extern "C" void kernel_launch(void* const* d_in, const int* in_sizes, int n_in,
                              void* d_out, int out_size){
    const float* x      = (const float*)d_in[0];
    const float* in_w   = (const float*)d_in[1];
    const float* conv_w = (const float*)d_in[2];
    const float* conv_b = (const float*)d_in[3];
    const float* xproj  = (const float*)d_in[4];
    const float* dtw    = (const float*)d_in[5];
    const float* dtb    = (const float*)d_in[6];
    const float* Alog   = (const float*)d_in[7];
    const float* Ds     = (const float*)d_in[8];
    const float* gam    = (const float*)d_in[9];
    const float* bet    = (const float*)d_in[10];
    const float* outw   = (const float*)d_in[11];
    float* out = (float*)d_out;

    k_inproj <<<dim3((2*DI)/64, (Bb*Ll)/64), 256>>>(x, in_w);
    launch_pdl(k_conv,    dim3(Bb*Ll), dim3(128), conv_w, conv_b);
    launch_pdl(k_cproj,   dim3(3, (Bb*Ll)/64, 2), dim3(256), xproj);
    launch_pdl(k_dts,     dim3(Ll/64, Kk, Bb), dim3(DI), dtw, dtb);
    launch_pdl(k_scanA,   dim3(Bb*Kk*NCHUNK), dim3(DI), Alog);
    launch_pdl(k_scanB,   dim3((Bb*Kk*DI*Ns)/256), dim3(256));
    launch_pdl(k_scanC,   dim3(Bb*Kk*NCHUNK), dim3(DI), Alog, Ds);
    launch_pdl(k_ln,      dim3(Bb*Ll), dim3(128), gam, bet, out, out_size);
    launch_pdl(k_outproj, dim3(DMo/64, (Bb*Ll)/64, 2), dim3(256), outw, out);
}